// round 9
// baseline (speedup 1.0000x reference)
#include <cuda_runtime.h>
#include <cuda_bf16.h>
#include <cstdint>

// ---------------------------------------------------------------------------
// GeneralizedRCNNExtractModel via HMMA (mma.sync bf16) split-fp32 GEMMs.
//   f6     = relu(x @ W6 + b6)            2000x12544 @ 12544x1024
//   f7     = relu(f6 @ W7 + b7)           2000x1024  @ 1024x1024
//   logits = f7 @ [Wcls|Wbox] + bias      2000x1024 @ 1024x405 (pad 512)
// fp32 emulated as bf16 split: A@B = Ah@Bh + Ah@Bl + Al@Bh.
// R9: 256x128 block tile (8 warps of 64x64, 1 CTA/SM, 144KB smem) —
// R8 was exactly smem/tensor balanced (1536 vs 1536 cyc/step); doubling M
// doubles tensor work per step while smem grows only 176KB (1408 cyc),
// breaking the parity so the tensor pipe becomes the sole limiter.
// ---------------------------------------------------------------------------

#define NUM_CLASSES 81
#define SCORE_THRESH 0.05f
#define BBOX_XFORM_CLIP 4.135166556742356f

#define RMAX 2000
#define KDIM 12544
#define HDIM 1024
#define NHEAD 512   // 405 used, padded

// --------------------------- device scratch -------------------------------
__device__ __nv_bfloat16 g_xh[RMAX * KDIM];
__device__ __nv_bfloat16 g_xl[RMAX * KDIM];
__device__ __nv_bfloat16 g_w6h[HDIM * KDIM];    // [N][K]
__device__ __nv_bfloat16 g_w6l[HDIM * KDIM];
__device__ __nv_bfloat16 g_w7h[HDIM * HDIM];
__device__ __nv_bfloat16 g_w7l[HDIM * HDIM];
__device__ __nv_bfloat16 g_whh[NHEAD * HDIM];   // rows 405..511 stay zero (.bss)
__device__ __nv_bfloat16 g_whl[NHEAD * HDIM];
__device__ __nv_bfloat16 g_f6h[RMAX * HDIM];
__device__ __nv_bfloat16 g_f6l[RMAX * HDIM];
__device__ __nv_bfloat16 g_f7h[RMAX * HDIM];
__device__ __nv_bfloat16 g_f7l[RMAX * HDIM];
__device__ float         g_part[2 * RMAX * HDIM];   // split-K partials

// --------------------------- PTX helpers ----------------------------------
__device__ __forceinline__ uint32_t smem_to_u32(const void* p) {
    uint32_t a;
    asm("{ .reg .u64 t; cvta.to.shared.u64 t, %1; cvt.u32.u64 %0, t; }"
        : "=r"(a) : "l"(p));
    return a;
}
__device__ __forceinline__ void cp_async16(uint32_t dst, const void* src, bool pred) {
    int sz = pred ? 16 : 0;
    asm volatile("cp.async.cg.shared.global [%0], [%1], 16, %2;"
                 :: "r"(dst), "l"(src), "r"(sz) : "memory");
}
#define CP_COMMIT() asm volatile("cp.async.commit_group;" ::: "memory")
#define CP_WAIT(N)  asm volatile("cp.async.wait_group %0;" :: "n"(N) : "memory")

__device__ __forceinline__ void ldsm_x4(uint32_t& r0, uint32_t& r1,
                                        uint32_t& r2, uint32_t& r3, uint32_t addr) {
    asm volatile("ldmatrix.sync.aligned.m8n8.x4.shared.b16 {%0,%1,%2,%3}, [%4];"
                 : "=r"(r0), "=r"(r1), "=r"(r2), "=r"(r3) : "r"(addr));
}
__device__ __forceinline__ void mma16816(float* c, const uint32_t* a,
                                         uint32_t b0, uint32_t b1) {
    asm volatile(
        "mma.sync.aligned.m16n8k16.row.col.f32.bf16.bf16.f32 "
        "{%0,%1,%2,%3}, {%4,%5,%6,%7}, {%8,%9}, {%0,%1,%2,%3};"
        : "+f"(c[0]), "+f"(c[1]), "+f"(c[2]), "+f"(c[3])
        : "r"(a[0]), "r"(a[1]), "r"(a[2]), "r"(a[3]), "r"(b0), "r"(b1));
}

// swizzled smem offset for (row, 16B-chunk), 64B logical rows.
__device__ __forceinline__ uint32_t swoff(int row, int chunk) {
    return (uint32_t)(row * 64 + ((chunk ^ ((row >> 1) & 3)) << 4));
}

// --------------------------- mega prep kernel -----------------------------
#define NBX 1024

__device__ void transpose_split_job(const float* __restrict__ W, int K, int Nsrc,
                                    int ldT, int rowoff,
                                    __nv_bfloat16* __restrict__ Th,
                                    __nv_bfloat16* __restrict__ Tl,
                                    int lb, int tid) {
    __shared__ float t[32][33];
    const int ntn = (Nsrc + 31) / 32;
    const int n0 = (lb % ntn) * 32;
    const int k0 = (lb / ntn) * 32;
    const int tx = tid & 31, ty = tid >> 5;  // 32 x 8
#pragma unroll
    for (int i = 0; i < 32; i += 8) {
        float v = 0.f;
        if (n0 + tx < Nsrc)
            v = W[(size_t)(k0 + ty + i) * Nsrc + n0 + tx];
        t[ty + i][tx] = v;
    }
    __syncthreads();
#pragma unroll
    for (int i = 0; i < 32; i += 8) {
        const int n = n0 + ty + i;
        if (n >= Nsrc) continue;
        float v = t[tx][ty + i];
        __nv_bfloat16 h = __float2bfloat16(v);
        __nv_bfloat16 l = __float2bfloat16(v - __bfloat162float(h));
        const size_t o = (size_t)(rowoff + n) * ldT + k0 + tx;
        Th[o] = h;
        Tl[o] = l;
    }
}

__global__ __launch_bounds__(256)
void prep_kernel(const float* __restrict__ x,
                 const float* __restrict__ W6,
                 const float* __restrict__ W7,
                 const float* __restrict__ Wcls,
                 const float* __restrict__ Wbox,
                 __nv_bfloat16* __restrict__ xh, __nv_bfloat16* __restrict__ xl,
                 __nv_bfloat16* __restrict__ w6h, __nv_bfloat16* __restrict__ w6l,
                 __nv_bfloat16* __restrict__ w7h, __nv_bfloat16* __restrict__ w7l,
                 __nv_bfloat16* __restrict__ whh, __nv_bfloat16* __restrict__ whl,
                 int M, int K1, int H, int NC) {
    const int tid = threadIdx.x;
    const int nbW6 = (H / 32) * (K1 / 32);
    const int nbW7 = (H / 32) * (H / 32);
    const int nbWc = ((NC + 31) / 32) * (H / 32);
    const int nbWb = ((NC * 4 + 31) / 32) * (H / 32);
    int b = blockIdx.x;

    if (b < NBX) {
        const size_t n4 = ((size_t)M * K1) / 4;
        size_t i = (size_t)b * 256 + tid;
        const size_t stride = (size_t)NBX * 256;
        const float4* X4 = reinterpret_cast<const float4*>(x);
        __nv_bfloat162* H2 = reinterpret_cast<__nv_bfloat162*>(xh);
        __nv_bfloat162* L2 = reinterpret_cast<__nv_bfloat162*>(xl);
        for (; i < n4; i += stride) {
            float4 v = X4[i];
            __nv_bfloat16 hx = __float2bfloat16(v.x), hy = __float2bfloat16(v.y);
            __nv_bfloat16 hz = __float2bfloat16(v.z), hw = __float2bfloat16(v.w);
            __nv_bfloat16 lx = __float2bfloat16(v.x - __bfloat162float(hx));
            __nv_bfloat16 ly = __float2bfloat16(v.y - __bfloat162float(hy));
            __nv_bfloat16 lz = __float2bfloat16(v.z - __bfloat162float(hz));
            __nv_bfloat16 lw = __float2bfloat16(v.w - __bfloat162float(hw));
            H2[i * 2 + 0] = __nv_bfloat162(hx, hy);
            H2[i * 2 + 1] = __nv_bfloat162(hz, hw);
            L2[i * 2 + 0] = __nv_bfloat162(lx, ly);
            L2[i * 2 + 1] = __nv_bfloat162(lz, lw);
        }
        return;
    }
    b -= NBX;
    if (b < nbW6) { transpose_split_job(W6, K1, H, K1, 0, w6h, w6l, b, tid); return; }
    b -= nbW6;
    if (b < nbW7) { transpose_split_job(W7, H, H, H, 0, w7h, w7l, b, tid); return; }
    b -= nbW7;
    if (b < nbWc) { transpose_split_job(Wcls, H, NC, H, 0, whh, whl, b, tid); return; }
    b -= nbWc;
    if (b < nbWb) { transpose_split_job(Wbox, H, NC * 4, H, NC, whh, whl, b, tid); return; }
}

// --------------------------- HMMA split GEMM (split-K) --------------------
// Partial[z][M][N] = sum over K-slice z of (Ah@Bh + Ah@Bl + Al@Bh).
// Block 256x128, 8 warps in 4x2 grid, warp tile 64x64 (128 acc regs).
// Stage = Ah 16K | Al 16K | Bh 8K | Bl 8K (48KB); 3-stage pipeline (144KB).
// 1 CTA/SM. Ksl%32==0, N%128==0, rows guarded vs M.
__global__ __launch_bounds__(256)
void hmma_gemm_split(int M, int N, int K, int Ksl,
                     const __nv_bfloat16* __restrict__ Ah,
                     const __nv_bfloat16* __restrict__ Al,
                     const __nv_bfloat16* __restrict__ Bh,
                     const __nv_bfloat16* __restrict__ Bl,
                     float* __restrict__ Pout) {
    extern __shared__ char smem[];
    const uint32_t sbase = smem_to_u32(smem);
    const int tid = threadIdx.x, lane = tid & 31, wid = tid >> 5;
    const int bm = blockIdx.y * 256, bn = blockIdx.x * 128;
    const int wm = (wid & 3) * 64, wn = (wid >> 2) * 64;
    const int kbase = blockIdx.z * Ksl;

    constexpr uint32_t STAGE = 49152u;   // Ah 16K | Al 16K | Bh 8K | Bl 8K
    constexpr uint32_t OAL = 16384u, OBH = 32768u, OBL = 40960u;
    constexpr int NSTAGE = 3;

    // ---- cp.async per-thread addressing ----
    // A tile: 256 rows x 4 chunks = 1024 slots -> 4 iters of 256 thr.
    uint32_t offA[4];
    size_t gofA[4];
    bool predA[4];
#pragma unroll
    for (int i = 0; i < 4; ++i) {
        const int idx = tid + i * 256;           // 0..1023
        const int row = idx >> 2, ch = idx & 3;  // 256 rows x 4 chunks(16B)
        offA[i] = swoff(row, ch);
        const int ra = (bm + row < M) ? (bm + row) : (M - 1);
        predA[i] = (bm + row < M);
        gofA[i] = (size_t)ra * K + kbase + ch * 8;
    }
    // B tile: 128 rows x 4 chunks = 512 slots -> 2 iters.
    uint32_t offB[2];
    size_t gofB[2];
#pragma unroll
    for (int i = 0; i < 2; ++i) {
        const int idx = tid + i * 256;
        const int row = idx >> 2, ch = idx & 3;
        offB[i] = swoff(row, ch);
        gofB[i] = (size_t)(bn + row) * K + kbase + ch * 8;
    }

    // ---- ldmatrix fragment offsets (within a tile) ----
    uint32_t aFrag[4][2];  // [mt][kc]
#pragma unroll
    for (int mt = 0; mt < 4; ++mt) {
        const int row = wm + mt * 16 + (lane & 15);
#pragma unroll
        for (int kc = 0; kc < 2; ++kc)
            aFrag[mt][kc] = swoff(row, (lane >> 4) + kc * 2);
    }
    uint32_t bFrag[4][2];  // [nt][kc]
#pragma unroll
    for (int nt = 0; nt < 4; ++nt) {
        const int row = wn + nt * 16 + ((lane & 7) | ((lane >> 4) << 3));
#pragma unroll
        for (int kc = 0; kc < 2; ++kc)
            bFrag[nt][kc] = swoff(row, ((lane >> 3) & 1) + kc * 2);
    }

    float acc[4][8][4];   // [mt][nf][4] = 128 regs
#pragma unroll
    for (int mt = 0; mt < 4; ++mt)
#pragma unroll
        for (int nf = 0; nf < 8; ++nf)
#pragma unroll
            for (int k = 0; k < 4; ++k) acc[mt][nf][k] = 0.f;

    const int S = Ksl / 32;

    auto issue = [&](int step) {
        const size_t k0 = (size_t)step * 32;
        const uint32_t st = (uint32_t)(step % NSTAGE) * STAGE;
#pragma unroll
        for (int i = 0; i < 4; ++i) {
            cp_async16(sbase + st + offA[i],       Ah + gofA[i] + k0, predA[i]);
            cp_async16(sbase + st + OAL + offA[i], Al + gofA[i] + k0, predA[i]);
        }
#pragma unroll
        for (int i = 0; i < 2; ++i) {
            cp_async16(sbase + st + OBH + offB[i], Bh + gofB[i] + k0, true);
            cp_async16(sbase + st + OBL + offB[i], Bl + gofB[i] + k0, true);
        }
        CP_COMMIT();
    };

    issue(0);
    if (S > 1) issue(1);

#pragma unroll 1
    for (int s = 0; s < S; ++s) {
        if (s + 1 < S) { CP_WAIT(1); } else { CP_WAIT(0); }
        __syncthreads();
        if (s + 2 < S) issue(s + 2);

        const uint32_t base   = sbase + (uint32_t)(s % NSTAGE) * STAGE;
        const uint32_t baseAl = base + OAL;
        const uint32_t baseBh = base + OBH;
        const uint32_t baseBl = base + OBL;
#pragma unroll
        for (int kc = 0; kc < 2; ++kc) {
            uint32_t aH[4][4], aL[4][4];
#pragma unroll
            for (int mt = 0; mt < 4; ++mt) {
                ldsm_x4(aH[mt][0], aH[mt][1], aH[mt][2], aH[mt][3],
                        base   + aFrag[mt][kc]);
                ldsm_x4(aL[mt][0], aL[mt][1], aL[mt][2], aL[mt][3],
                        baseAl + aFrag[mt][kc]);
            }
#pragma unroll
            for (int nt = 0; nt < 4; ++nt) {
                uint32_t bh0, bh1, bh2, bh3, bl0, bl1, bl2, bl3;
                ldsm_x4(bh0, bh1, bh2, bh3, baseBh + bFrag[nt][kc]);
                ldsm_x4(bl0, bl1, bl2, bl3, baseBl + bFrag[nt][kc]);
#pragma unroll
                for (int mt = 0; mt < 4; ++mt) {
                    float* a0 = acc[mt][nt * 2 + 0];
                    float* a1 = acc[mt][nt * 2 + 1];
                    // Ah @ Bh
                    mma16816(a0, aH[mt], bh0, bh1);
                    mma16816(a1, aH[mt], bh2, bh3);
                    // Ah @ Bl
                    mma16816(a0, aH[mt], bl0, bl1);
                    mma16816(a1, aH[mt], bl2, bl3);
                    // Al @ Bh
                    mma16816(a0, aL[mt], bh0, bh1);
                    mma16816(a1, aL[mt], bh2, bh3);
                }
            }
        }
    }

    // ---- epilogue: raw partials to Pout[z] ----
    float* P = Pout + (size_t)blockIdx.z * M * N;
#pragma unroll
    for (int mt = 0; mt < 4; ++mt) {
#pragma unroll
        for (int nf = 0; nf < 8; ++nf) {
            const int col = bn + wn + nf * 8 + (lane & 3) * 2;
#pragma unroll
            for (int half = 0; half < 2; ++half) {
                const int row = bm + wm + mt * 16 + (lane >> 2) + half * 8;
                if (row >= M) continue;
                *reinterpret_cast<float2*>(&P[(size_t)row * N + col]) =
                    make_float2(acc[mt][nf][half * 2 + 0],
                                acc[mt][nf][half * 2 + 1]);
            }
        }
    }
}

// --------------------------- split-K reduce + epilogue --------------------
__global__ __launch_bounds__(256)
void reduce_epilogue(int M, int N,
                     const float* __restrict__ P,
                     const float* __restrict__ bias, int do_relu,
                     float* __restrict__ C, int ldc,
                     __nv_bfloat16* __restrict__ Oh,
                     __nv_bfloat16* __restrict__ Ol, int ldo) {
    const size_t i = (size_t)blockIdx.x * blockDim.x + threadIdx.x;
    const size_t n2 = (size_t)M * N / 2;
    if (i >= n2) return;
    const float2 p0 = reinterpret_cast<const float2*>(P)[i];
    const float2 p1 = reinterpret_cast<const float2*>(P + (size_t)M * N)[i];
    const int col = (int)((i * 2) % N);
    const int row = (int)((i * 2) / N);
    float v0 = p0.x + p1.x + bias[col];
    float v1 = p0.y + p1.y + bias[col + 1];
    if (do_relu) { v0 = fmaxf(v0, 0.f); v1 = fmaxf(v1, 0.f); }
    if (C)
        *reinterpret_cast<float2*>(&C[(size_t)row * ldc + col]) =
            make_float2(v0, v1);
    if (Oh) {
        __nv_bfloat16 h0 = __float2bfloat16(v0);
        __nv_bfloat16 h1 = __float2bfloat16(v1);
        __nv_bfloat16 l0 = __float2bfloat16(v0 - __bfloat162float(h0));
        __nv_bfloat16 l1 = __float2bfloat16(v1 - __bfloat162float(h1));
        *reinterpret_cast<__nv_bfloat162*>(&Oh[(size_t)row * ldo + col]) =
            __nv_bfloat162(h0, h1);
        *reinterpret_cast<__nv_bfloat162*>(&Ol[(size_t)row * ldo + col]) =
            __nv_bfloat162(l0, l1);
    }
}

// --------------------------- postprocess (+head reduce) -------------------
__global__ __launch_bounds__(128)
void postprocess_kernel(int M,
                        const float* __restrict__ P,   // [2][M][NHEAD]
                        const float* __restrict__ bcls,
                        const float* __restrict__ bbox_b,
                        const float* __restrict__ boxes,
                        float* __restrict__ out, int ldo) {
    const int r = blockIdx.x;
    const int t = threadIdx.x;
    __shared__ float sl[NUM_CLASSES * 5];  // 405
    __shared__ float smax, ssum;

    const float* p0 = P + (size_t)r * NHEAD;
    const float* p1 = P + (size_t)M * NHEAD + (size_t)r * NHEAD;
    for (int i = t; i < NUM_CLASSES * 5; i += 128) {
        const float bias = (i < NUM_CLASSES) ? bcls[i] : bbox_b[i - NUM_CLASSES];
        sl[i] = p0[i] + p1[i] + bias;
    }
    __syncthreads();

    if (t == 0) {
        float m = -1e30f;
        for (int i = 0; i < NUM_CLASSES; ++i) m = fmaxf(m, sl[i]);
        float s = 0.f;
        for (int i = 0; i < NUM_CLASSES; ++i) s += expf(sl[i] - m);
        smax = m;
        ssum = s;
    }
    __syncthreads();

    if (t < NUM_CLASSES - 1) {
        const int j = t + 1;
        const float p = expf(sl[j] - smax) / ssum;
        const bool keep = p > SCORE_THRESH;

        const float bx0 = boxes[r * 4 + 0];
        const float by0 = boxes[r * 4 + 1];
        const float bx1 = boxes[r * 4 + 2];
        const float by1 = boxes[r * 4 + 3];
        const float w = bx1 - bx0 + 1.0f;
        const float hh = by1 - by0 + 1.0f;
        const float cx = bx0 + 0.5f * w;
        const float cy = by0 + 0.5f * hh;

        const float* reg = &sl[NUM_CLASSES + j * 4];
        const float dx = reg[0] * 0.1f;
        const float dy = reg[1] * 0.1f;
        const float dw = fminf(reg[2] * 0.2f, BBOX_XFORM_CLIP);
        const float dh = fminf(reg[3] * 0.2f, BBOX_XFORM_CLIP);

        const float pcx = dx * w + cx;
        const float pcy = dy * hh + cy;
        const float pw = expf(dw) * w;
        const float ph = expf(dh) * hh;

        float* orow = out + (size_t)r * ldo;
        orow[t] = keep ? p : 0.f;
        const int bo = (NUM_CLASSES - 1) + t * 4;
        orow[bo + 0] = keep ? (pcx - 0.5f * pw) : 0.f;
        orow[bo + 1] = keep ? (pcy - 0.5f * ph) : 0.f;
        orow[bo + 2] = keep ? (pcx + 0.5f * pw - 1.0f) : 0.f;
        orow[bo + 3] = keep ? (pcy + 0.5f * ph - 1.0f) : 0.f;
    }
}

// --------------------------- launch ---------------------------------------
extern "C" void kernel_launch(void* const* d_in, const int* in_sizes, int n_in,
                              void* d_out, int out_size) {
    const float* x      = (const float*)d_in[0];
    const float* boxes  = (const float*)d_in[1];
    const float* W6     = (const float*)d_in[2];
    const float* b6     = (const float*)d_in[3];
    const float* W7     = (const float*)d_in[4];
    const float* b7     = (const float*)d_in[5];
    const float* Wcls   = (const float*)d_in[6];
    const float* bcls   = (const float*)d_in[7];
    const float* Wbox   = (const float*)d_in[8];
    const float* bbox_b = (const float*)d_in[9];
    float* out = (float*)d_out;
    (void)n_in; (void)out_size;

    const int M  = in_sizes[1] / 4;       // 2000
    const int K1 = in_sizes[0] / M;       // 12544
    const int H  = in_sizes[3];           // 1024
    const int NC = in_sizes[7];           // 81
    const int OUTW = (NC - 1) * 5 + H;    // 1424

    __nv_bfloat16 *xh, *xl, *w6h, *w6l, *w7h, *w7l, *whh, *whl;
    __nv_bfloat16 *f6h, *f6l, *f7h, *f7l;
    float *part;
    cudaGetSymbolAddress((void**)&xh, g_xh);
    cudaGetSymbolAddress((void**)&xl, g_xl);
    cudaGetSymbolAddress((void**)&w6h, g_w6h);
    cudaGetSymbolAddress((void**)&w6l, g_w6l);
    cudaGetSymbolAddress((void**)&w7h, g_w7h);
    cudaGetSymbolAddress((void**)&w7l, g_w7l);
    cudaGetSymbolAddress((void**)&whh, g_whh);
    cudaGetSymbolAddress((void**)&whl, g_whl);
    cudaGetSymbolAddress((void**)&f6h, g_f6h);
    cudaGetSymbolAddress((void**)&f6l, g_f6l);
    cudaGetSymbolAddress((void**)&f7h, g_f7h);
    cudaGetSymbolAddress((void**)&f7l, g_f7l);
    cudaGetSymbolAddress((void**)&part, g_part);

    const int SMEM_BYTES = 3 * 49152;  // 144KB
    cudaFuncSetAttribute(hmma_gemm_split,
                         cudaFuncAttributeMaxDynamicSharedMemorySize, SMEM_BYTES);

    // 1) mega prep
    {
        const int nbW6 = (H / 32) * (K1 / 32);
        const int nbW7 = (H / 32) * (H / 32);
        const int nbWc = ((NC + 31) / 32) * (H / 32);
        const int nbWb = ((NC * 4 + 31) / 32) * (H / 32);
        const int nb = NBX + nbW6 + nbW7 + nbWc + nbWb;
        prep_kernel<<<nb, 256>>>(x, W6, W7, Wcls, Wbox,
                                 xh, xl, w6h, w6l, w7h, w7l, whh, whl,
                                 M, K1, H, NC);
    }

    const int MB = (M + 255) / 256;  // 8
    // 2) GEMM1 (split-K=2) + reduce -> f6 (out cols [400,1424)) + split copy
    hmma_gemm_split<<<dim3(H / 128, MB, 2), 256, SMEM_BYTES>>>(
        M, H, K1, K1 / 2, xh, xl, w6h, w6l, part);
    reduce_epilogue<<<(M * H / 2 + 255) / 256, 256>>>(
        M, H, part, b6, 1, out + (NC - 1) * 5, OUTW, f6h, f6l, H);
    // 3) GEMM2 (split-K=2) + reduce -> f7 split
    hmma_gemm_split<<<dim3(H / 128, MB, 2), 256, SMEM_BYTES>>>(
        M, H, H, H / 2, f6h, f6l, w7h, w7l, part);
    reduce_epilogue<<<(M * H / 2 + 255) / 256, 256>>>(
        M, H, part, b7, 1, nullptr, 0, f7h, f7l, H);
    // 4) head GEMM (split-K=2); reduce fused into postprocess
    hmma_gemm_split<<<dim3(NHEAD / 128, MB, 2), 256, SMEM_BYTES>>>(
        M, NHEAD, H, H / 2, f7h, f7l, whh, whl, part);
    // 5) postprocess (+head reduce + bias)
    postprocess_kernel<<<M, 128>>>(M, part, bcls, bbox_b, boxes, out, OUTW);
}

// round 10
// speedup vs baseline: 1.0728x; 1.0728x over previous
#include <cuda_runtime.h>
#include <cuda_bf16.h>
#include <cstdint>

// ---------------------------------------------------------------------------
// GeneralizedRCNNExtractModel via HMMA (mma.sync bf16) split-fp32 GEMMs.
//   f6     = relu(x @ W6 + b6)            2000x12544 @ 12544x1024
//   f7     = relu(f6 @ W7 + b7)           2000x1024  @ 1024x1024
//   logits = f7 @ [Wcls|Wbox] + bias      2000x1024 @ 1024x405 (pad 512)
// fp32 emulated as bf16 split: A@B = Ah@Bh + Ah@Bl + Al@Bh.
// R10: R8 config (128x128, 4 warps of 64x64, 2 CTAs/SM) with the inner
// loop reordered combo-outer: same-accumulator MMA reuse distance 2 -> 8,
// breaking the acc-RAW chain that pinned tensor% at ~54% across R7-R9.
// ---------------------------------------------------------------------------

#define NUM_CLASSES 81
#define SCORE_THRESH 0.05f
#define BBOX_XFORM_CLIP 4.135166556742356f

#define RMAX 2000
#define KDIM 12544
#define HDIM 1024
#define NHEAD 512   // 405 used, padded

// --------------------------- device scratch -------------------------------
__device__ __nv_bfloat16 g_xh[RMAX * KDIM];
__device__ __nv_bfloat16 g_xl[RMAX * KDIM];
__device__ __nv_bfloat16 g_w6h[HDIM * KDIM];    // [N][K]
__device__ __nv_bfloat16 g_w6l[HDIM * KDIM];
__device__ __nv_bfloat16 g_w7h[HDIM * HDIM];
__device__ __nv_bfloat16 g_w7l[HDIM * HDIM];
__device__ __nv_bfloat16 g_whh[NHEAD * HDIM];   // rows 405..511 stay zero (.bss)
__device__ __nv_bfloat16 g_whl[NHEAD * HDIM];
__device__ __nv_bfloat16 g_f6h[RMAX * HDIM];
__device__ __nv_bfloat16 g_f6l[RMAX * HDIM];
__device__ __nv_bfloat16 g_f7h[RMAX * HDIM];
__device__ __nv_bfloat16 g_f7l[RMAX * HDIM];
__device__ float         g_part[2 * RMAX * HDIM];   // split-K partials

// --------------------------- PTX helpers ----------------------------------
__device__ __forceinline__ uint32_t smem_to_u32(const void* p) {
    uint32_t a;
    asm("{ .reg .u64 t; cvta.to.shared.u64 t, %1; cvt.u32.u64 %0, t; }"
        : "=r"(a) : "l"(p));
    return a;
}
__device__ __forceinline__ void cp_async16(uint32_t dst, const void* src, bool pred) {
    int sz = pred ? 16 : 0;
    asm volatile("cp.async.cg.shared.global [%0], [%1], 16, %2;"
                 :: "r"(dst), "l"(src), "r"(sz) : "memory");
}
#define CP_COMMIT() asm volatile("cp.async.commit_group;" ::: "memory")
#define CP_WAIT(N)  asm volatile("cp.async.wait_group %0;" :: "n"(N) : "memory")

__device__ __forceinline__ void ldsm_x4(uint32_t& r0, uint32_t& r1,
                                        uint32_t& r2, uint32_t& r3, uint32_t addr) {
    asm volatile("ldmatrix.sync.aligned.m8n8.x4.shared.b16 {%0,%1,%2,%3}, [%4];"
                 : "=r"(r0), "=r"(r1), "=r"(r2), "=r"(r3) : "r"(addr));
}
__device__ __forceinline__ void mma16816(float* c, const uint32_t* a,
                                         uint32_t b0, uint32_t b1) {
    asm volatile(
        "mma.sync.aligned.m16n8k16.row.col.f32.bf16.bf16.f32 "
        "{%0,%1,%2,%3}, {%4,%5,%6,%7}, {%8,%9}, {%0,%1,%2,%3};"
        : "+f"(c[0]), "+f"(c[1]), "+f"(c[2]), "+f"(c[3])
        : "r"(a[0]), "r"(a[1]), "r"(a[2]), "r"(a[3]), "r"(b0), "r"(b1));
}

// swizzled smem offset for (row, 16B-chunk), 64B logical rows.
__device__ __forceinline__ uint32_t swoff(int row, int chunk) {
    return (uint32_t)(row * 64 + ((chunk ^ ((row >> 1) & 3)) << 4));
}

// --------------------------- mega prep kernel -----------------------------
#define NBX 1024

__device__ void transpose_split_job(const float* __restrict__ W, int K, int Nsrc,
                                    int ldT, int rowoff,
                                    __nv_bfloat16* __restrict__ Th,
                                    __nv_bfloat16* __restrict__ Tl,
                                    int lb, int tid) {
    __shared__ float t[32][33];
    const int ntn = (Nsrc + 31) / 32;
    const int n0 = (lb % ntn) * 32;
    const int k0 = (lb / ntn) * 32;
    const int tx = tid & 31, ty = tid >> 5;  // 32 x 8
#pragma unroll
    for (int i = 0; i < 32; i += 8) {
        float v = 0.f;
        if (n0 + tx < Nsrc)
            v = W[(size_t)(k0 + ty + i) * Nsrc + n0 + tx];
        t[ty + i][tx] = v;
    }
    __syncthreads();
#pragma unroll
    for (int i = 0; i < 32; i += 8) {
        const int n = n0 + ty + i;
        if (n >= Nsrc) continue;
        float v = t[tx][ty + i];
        __nv_bfloat16 h = __float2bfloat16(v);
        __nv_bfloat16 l = __float2bfloat16(v - __bfloat162float(h));
        const size_t o = (size_t)(rowoff + n) * ldT + k0 + tx;
        Th[o] = h;
        Tl[o] = l;
    }
}

__global__ __launch_bounds__(256)
void prep_kernel(const float* __restrict__ x,
                 const float* __restrict__ W6,
                 const float* __restrict__ W7,
                 const float* __restrict__ Wcls,
                 const float* __restrict__ Wbox,
                 __nv_bfloat16* __restrict__ xh, __nv_bfloat16* __restrict__ xl,
                 __nv_bfloat16* __restrict__ w6h, __nv_bfloat16* __restrict__ w6l,
                 __nv_bfloat16* __restrict__ w7h, __nv_bfloat16* __restrict__ w7l,
                 __nv_bfloat16* __restrict__ whh, __nv_bfloat16* __restrict__ whl,
                 int M, int K1, int H, int NC) {
    const int tid = threadIdx.x;
    const int nbW6 = (H / 32) * (K1 / 32);
    const int nbW7 = (H / 32) * (H / 32);
    const int nbWc = ((NC + 31) / 32) * (H / 32);
    const int nbWb = ((NC * 4 + 31) / 32) * (H / 32);
    int b = blockIdx.x;

    if (b < NBX) {
        const size_t n4 = ((size_t)M * K1) / 4;
        size_t i = (size_t)b * 256 + tid;
        const size_t stride = (size_t)NBX * 256;
        const float4* X4 = reinterpret_cast<const float4*>(x);
        __nv_bfloat162* H2 = reinterpret_cast<__nv_bfloat162*>(xh);
        __nv_bfloat162* L2 = reinterpret_cast<__nv_bfloat162*>(xl);
        for (; i < n4; i += stride) {
            float4 v = X4[i];
            __nv_bfloat16 hx = __float2bfloat16(v.x), hy = __float2bfloat16(v.y);
            __nv_bfloat16 hz = __float2bfloat16(v.z), hw = __float2bfloat16(v.w);
            __nv_bfloat16 lx = __float2bfloat16(v.x - __bfloat162float(hx));
            __nv_bfloat16 ly = __float2bfloat16(v.y - __bfloat162float(hy));
            __nv_bfloat16 lz = __float2bfloat16(v.z - __bfloat162float(hz));
            __nv_bfloat16 lw = __float2bfloat16(v.w - __bfloat162float(hw));
            H2[i * 2 + 0] = __nv_bfloat162(hx, hy);
            H2[i * 2 + 1] = __nv_bfloat162(hz, hw);
            L2[i * 2 + 0] = __nv_bfloat162(lx, ly);
            L2[i * 2 + 1] = __nv_bfloat162(lz, lw);
        }
        return;
    }
    b -= NBX;
    if (b < nbW6) { transpose_split_job(W6, K1, H, K1, 0, w6h, w6l, b, tid); return; }
    b -= nbW6;
    if (b < nbW7) { transpose_split_job(W7, H, H, H, 0, w7h, w7l, b, tid); return; }
    b -= nbW7;
    if (b < nbWc) { transpose_split_job(Wcls, H, NC, H, 0, whh, whl, b, tid); return; }
    b -= nbWc;
    if (b < nbWb) { transpose_split_job(Wbox, H, NC * 4, H, NC, whh, whl, b, tid); return; }
}

// --------------------------- HMMA split GEMM (split-K) --------------------
// Partial[z][M][N] = sum over K-slice z of (Ah@Bh + Ah@Bl + Al@Bh).
// Block 128x128, 4 warps in 2x2 grid, warp tile 64x64 (128 acc regs).
// Stage = Ah|Al|Bh|Bl (32KB), 3-stage cp.async pipeline (96KB smem),
// 2 CTAs/SM. MMAs ordered combo-outer/mt-inner so each accumulator's
// reuse distance is 8 MMAs (acc-RAW chain broken). Ksl%32==0, N%128==0.
__global__ __launch_bounds__(128, 2)
void hmma_gemm_split(int M, int N, int K, int Ksl,
                     const __nv_bfloat16* __restrict__ Ah,
                     const __nv_bfloat16* __restrict__ Al,
                     const __nv_bfloat16* __restrict__ Bh,
                     const __nv_bfloat16* __restrict__ Bl,
                     float* __restrict__ Pout) {
    extern __shared__ char smem[];
    const uint32_t sbase = smem_to_u32(smem);
    const int tid = threadIdx.x, lane = tid & 31, wid = tid >> 5;
    const int bm = blockIdx.y * 128, bn = blockIdx.x * 128;
    const int wm = (wid & 1) * 64, wn = (wid >> 1) * 64;
    const int kbase = blockIdx.z * Ksl;

    constexpr uint32_t STAGE = 32768u;   // Ah 8K | Al 8K | Bh 8K | Bl 8K
    constexpr int NSTAGE = 3;

    // ---- cp.async per-thread addressing: 128 thr x 4 iters covers 8KB tile
    uint32_t offA[4];
    size_t gofA[4], gofB[4];
    bool predA[4];
#pragma unroll
    for (int i = 0; i < 4; ++i) {
        const int idx = tid + i * 128;           // 0..511
        const int row = idx >> 2, ch = idx & 3;  // 128 rows x 4 chunks(16B)
        offA[i] = swoff(row, ch);
        const int ra = (bm + row < M) ? (bm + row) : (M - 1);
        predA[i] = (bm + row < M);
        gofA[i] = (size_t)ra * K + kbase + ch * 8;
        gofB[i] = (size_t)(bn + row) * K + kbase + ch * 8;
    }

    // ---- ldmatrix fragment offsets (within a tile) ----
    uint32_t aFrag[4][2];  // [mt][kc]
#pragma unroll
    for (int mt = 0; mt < 4; ++mt) {
        const int row = wm + mt * 16 + (lane & 15);
#pragma unroll
        for (int kc = 0; kc < 2; ++kc)
            aFrag[mt][kc] = swoff(row, (lane >> 4) + kc * 2);
    }
    uint32_t bFrag[4][2];  // [nt][kc]
#pragma unroll
    for (int nt = 0; nt < 4; ++nt) {
        const int row = wn + nt * 16 + ((lane & 7) | ((lane >> 4) << 3));
#pragma unroll
        for (int kc = 0; kc < 2; ++kc)
            bFrag[nt][kc] = swoff(row, ((lane >> 3) & 1) + kc * 2);
    }

    float acc[4][8][4];   // [mt][nf][4] = 128 regs
#pragma unroll
    for (int mt = 0; mt < 4; ++mt)
#pragma unroll
        for (int nf = 0; nf < 8; ++nf)
#pragma unroll
            for (int k = 0; k < 4; ++k) acc[mt][nf][k] = 0.f;

    const int S = Ksl / 32;

    auto issue = [&](int step) {
        const size_t k0 = (size_t)step * 32;
        const uint32_t st = (uint32_t)(step % NSTAGE) * STAGE;
#pragma unroll
        for (int i = 0; i < 4; ++i) {
            cp_async16(sbase + st + offA[i],          Ah + gofA[i] + k0, predA[i]);
            cp_async16(sbase + st + 8192 + offA[i],   Al + gofA[i] + k0, predA[i]);
            cp_async16(sbase + st + 16384 + offA[i],  Bh + gofB[i] + k0, true);
            cp_async16(sbase + st + 24576 + offA[i],  Bl + gofB[i] + k0, true);
        }
        CP_COMMIT();
    };

    issue(0);
    if (S > 1) issue(1);

#pragma unroll 1
    for (int s = 0; s < S; ++s) {
        if (s + 1 < S) { CP_WAIT(1); } else { CP_WAIT(0); }
        __syncthreads();
        if (s + 2 < S) issue(s + 2);

        const uint32_t base   = sbase + (uint32_t)(s % NSTAGE) * STAGE;
        const uint32_t baseAl = base + 8192u;
        const uint32_t baseBh = base + 16384u;
        const uint32_t baseBl = base + 24576u;
#pragma unroll
        for (int kc = 0; kc < 2; ++kc) {
            uint32_t aH[4][4], aL[4][4];
#pragma unroll
            for (int mt = 0; mt < 4; ++mt) {
                ldsm_x4(aH[mt][0], aH[mt][1], aH[mt][2], aH[mt][3],
                        base   + aFrag[mt][kc]);
                ldsm_x4(aL[mt][0], aL[mt][1], aL[mt][2], aL[mt][3],
                        baseAl + aFrag[mt][kc]);
            }
#pragma unroll
            for (int nt = 0; nt < 4; ++nt) {
                uint32_t bh0, bh1, bh2, bh3, bl0, bl1, bl2, bl3;
                ldsm_x4(bh0, bh1, bh2, bh3, baseBh + bFrag[nt][kc]);
                ldsm_x4(bl0, bl1, bl2, bl3, baseBl + bFrag[nt][kc]);
                // combo-outer ordering: 8 independent accs per combo,
                // same-acc reuse distance = 8 MMAs.
                // ---- Ah @ Bh ----
#pragma unroll
                for (int mt = 0; mt < 4; ++mt) {
                    mma16816(acc[mt][nt * 2 + 0], aH[mt], bh0, bh1);
                    mma16816(acc[mt][nt * 2 + 1], aH[mt], bh2, bh3);
                }
                // ---- Ah @ Bl ----
#pragma unroll
                for (int mt = 0; mt < 4; ++mt) {
                    mma16816(acc[mt][nt * 2 + 0], aH[mt], bl0, bl1);
                    mma16816(acc[mt][nt * 2 + 1], aH[mt], bl2, bl3);
                }
                // ---- Al @ Bh ----
#pragma unroll
                for (int mt = 0; mt < 4; ++mt) {
                    mma16816(acc[mt][nt * 2 + 0], aL[mt], bh0, bh1);
                    mma16816(acc[mt][nt * 2 + 1], aL[mt], bh2, bh3);
                }
            }
        }
    }

    // ---- epilogue: raw partials to Pout[z] ----
    float* P = Pout + (size_t)blockIdx.z * M * N;
#pragma unroll
    for (int mt = 0; mt < 4; ++mt) {
#pragma unroll
        for (int nf = 0; nf < 8; ++nf) {
            const int col = bn + wn + nf * 8 + (lane & 3) * 2;
#pragma unroll
            for (int half = 0; half < 2; ++half) {
                const int row = bm + wm + mt * 16 + (lane >> 2) + half * 8;
                if (row >= M) continue;
                *reinterpret_cast<float2*>(&P[(size_t)row * N + col]) =
                    make_float2(acc[mt][nf][half * 2 + 0],
                                acc[mt][nf][half * 2 + 1]);
            }
        }
    }
}

// --------------------------- split-K reduce + epilogue --------------------
__global__ __launch_bounds__(256)
void reduce_epilogue(int M, int N,
                     const float* __restrict__ P,
                     const float* __restrict__ bias, int do_relu,
                     float* __restrict__ C, int ldc,
                     __nv_bfloat16* __restrict__ Oh,
                     __nv_bfloat16* __restrict__ Ol, int ldo) {
    const size_t i = (size_t)blockIdx.x * blockDim.x + threadIdx.x;
    const size_t n2 = (size_t)M * N / 2;
    if (i >= n2) return;
    const float2 p0 = reinterpret_cast<const float2*>(P)[i];
    const float2 p1 = reinterpret_cast<const float2*>(P + (size_t)M * N)[i];
    const int col = (int)((i * 2) % N);
    const int row = (int)((i * 2) / N);
    float v0 = p0.x + p1.x + bias[col];
    float v1 = p0.y + p1.y + bias[col + 1];
    if (do_relu) { v0 = fmaxf(v0, 0.f); v1 = fmaxf(v1, 0.f); }
    if (C)
        *reinterpret_cast<float2*>(&C[(size_t)row * ldc + col]) =
            make_float2(v0, v1);
    if (Oh) {
        __nv_bfloat16 h0 = __float2bfloat16(v0);
        __nv_bfloat16 h1 = __float2bfloat16(v1);
        __nv_bfloat16 l0 = __float2bfloat16(v0 - __bfloat162float(h0));
        __nv_bfloat16 l1 = __float2bfloat16(v1 - __bfloat162float(h1));
        *reinterpret_cast<__nv_bfloat162*>(&Oh[(size_t)row * ldo + col]) =
            __nv_bfloat162(h0, h1);
        *reinterpret_cast<__nv_bfloat162*>(&Ol[(size_t)row * ldo + col]) =
            __nv_bfloat162(l0, l1);
    }
}

// --------------------------- postprocess (+head reduce) -------------------
__global__ __launch_bounds__(128)
void postprocess_kernel(int M,
                        const float* __restrict__ P,   // [2][M][NHEAD]
                        const float* __restrict__ bcls,
                        const float* __restrict__ bbox_b,
                        const float* __restrict__ boxes,
                        float* __restrict__ out, int ldo) {
    const int r = blockIdx.x;
    const int t = threadIdx.x;
    __shared__ float sl[NUM_CLASSES * 5];  // 405
    __shared__ float smax, ssum;

    const float* p0 = P + (size_t)r * NHEAD;
    const float* p1 = P + (size_t)M * NHEAD + (size_t)r * NHEAD;
    for (int i = t; i < NUM_CLASSES * 5; i += 128) {
        const float bias = (i < NUM_CLASSES) ? bcls[i] : bbox_b[i - NUM_CLASSES];
        sl[i] = p0[i] + p1[i] + bias;
    }
    __syncthreads();

    if (t == 0) {
        float m = -1e30f;
        for (int i = 0; i < NUM_CLASSES; ++i) m = fmaxf(m, sl[i]);
        float s = 0.f;
        for (int i = 0; i < NUM_CLASSES; ++i) s += expf(sl[i] - m);
        smax = m;
        ssum = s;
    }
    __syncthreads();

    if (t < NUM_CLASSES - 1) {
        const int j = t + 1;
        const float p = expf(sl[j] - smax) / ssum;
        const bool keep = p > SCORE_THRESH;

        const float bx0 = boxes[r * 4 + 0];
        const float by0 = boxes[r * 4 + 1];
        const float bx1 = boxes[r * 4 + 2];
        const float by1 = boxes[r * 4 + 3];
        const float w = bx1 - bx0 + 1.0f;
        const float hh = by1 - by0 + 1.0f;
        const float cx = bx0 + 0.5f * w;
        const float cy = by0 + 0.5f * hh;

        const float* reg = &sl[NUM_CLASSES + j * 4];
        const float dx = reg[0] * 0.1f;
        const float dy = reg[1] * 0.1f;
        const float dw = fminf(reg[2] * 0.2f, BBOX_XFORM_CLIP);
        const float dh = fminf(reg[3] * 0.2f, BBOX_XFORM_CLIP);

        const float pcx = dx * w + cx;
        const float pcy = dy * hh + cy;
        const float pw = expf(dw) * w;
        const float ph = expf(dh) * hh;

        float* orow = out + (size_t)r * ldo;
        orow[t] = keep ? p : 0.f;
        const int bo = (NUM_CLASSES - 1) + t * 4;
        orow[bo + 0] = keep ? (pcx - 0.5f * pw) : 0.f;
        orow[bo + 1] = keep ? (pcy - 0.5f * ph) : 0.f;
        orow[bo + 2] = keep ? (pcx + 0.5f * pw - 1.0f) : 0.f;
        orow[bo + 3] = keep ? (pcy + 0.5f * ph - 1.0f) : 0.f;
    }
}

// --------------------------- launch ---------------------------------------
extern "C" void kernel_launch(void* const* d_in, const int* in_sizes, int n_in,
                              void* d_out, int out_size) {
    const float* x      = (const float*)d_in[0];
    const float* boxes  = (const float*)d_in[1];
    const float* W6     = (const float*)d_in[2];
    const float* b6     = (const float*)d_in[3];
    const float* W7     = (const float*)d_in[4];
    const float* b7     = (const float*)d_in[5];
    const float* Wcls   = (const float*)d_in[6];
    const float* bcls   = (const float*)d_in[7];
    const float* Wbox   = (const float*)d_in[8];
    const float* bbox_b = (const float*)d_in[9];
    float* out = (float*)d_out;
    (void)n_in; (void)out_size;

    const int M  = in_sizes[1] / 4;       // 2000
    const int K1 = in_sizes[0] / M;       // 12544
    const int H  = in_sizes[3];           // 1024
    const int NC = in_sizes[7];           // 81
    const int OUTW = (NC - 1) * 5 + H;    // 1424

    __nv_bfloat16 *xh, *xl, *w6h, *w6l, *w7h, *w7l, *whh, *whl;
    __nv_bfloat16 *f6h, *f6l, *f7h, *f7l;
    float *part;
    cudaGetSymbolAddress((void**)&xh, g_xh);
    cudaGetSymbolAddress((void**)&xl, g_xl);
    cudaGetSymbolAddress((void**)&w6h, g_w6h);
    cudaGetSymbolAddress((void**)&w6l, g_w6l);
    cudaGetSymbolAddress((void**)&w7h, g_w7h);
    cudaGetSymbolAddress((void**)&w7l, g_w7l);
    cudaGetSymbolAddress((void**)&whh, g_whh);
    cudaGetSymbolAddress((void**)&whl, g_whl);
    cudaGetSymbolAddress((void**)&f6h, g_f6h);
    cudaGetSymbolAddress((void**)&f6l, g_f6l);
    cudaGetSymbolAddress((void**)&f7h, g_f7h);
    cudaGetSymbolAddress((void**)&f7l, g_f7l);
    cudaGetSymbolAddress((void**)&part, g_part);

    const int SMEM_BYTES = 3 * 32768;  // 96KB
    cudaFuncSetAttribute(hmma_gemm_split,
                         cudaFuncAttributeMaxDynamicSharedMemorySize, SMEM_BYTES);

    // 1) mega prep
    {
        const int nbW6 = (H / 32) * (K1 / 32);
        const int nbW7 = (H / 32) * (H / 32);
        const int nbWc = ((NC + 31) / 32) * (H / 32);
        const int nbWb = ((NC * 4 + 31) / 32) * (H / 32);
        const int nb = NBX + nbW6 + nbW7 + nbWc + nbWb;
        prep_kernel<<<nb, 256>>>(x, W6, W7, Wcls, Wbox,
                                 xh, xl, w6h, w6l, w7h, w7l, whh, whl,
                                 M, K1, H, NC);
    }

    const int MB = (M + 127) / 128;  // 16
    // 2) GEMM1 (split-K=2) + reduce -> f6 (out cols [400,1424)) + split copy
    hmma_gemm_split<<<dim3(H / 128, MB, 2), 128, SMEM_BYTES>>>(
        M, H, K1, K1 / 2, xh, xl, w6h, w6l, part);
    reduce_epilogue<<<(M * H / 2 + 255) / 256, 256>>>(
        M, H, part, b6, 1, out + (NC - 1) * 5, OUTW, f6h, f6l, H);
    // 3) GEMM2 (split-K=2) + reduce -> f7 split
    hmma_gemm_split<<<dim3(H / 128, MB, 2), 128, SMEM_BYTES>>>(
        M, H, H, H / 2, f6h, f6l, w7h, w7l, part);
    reduce_epilogue<<<(M * H / 2 + 255) / 256, 256>>>(
        M, H, part, b7, 1, nullptr, 0, f7h, f7l, H);
    // 4) head GEMM (split-K=2); reduce fused into postprocess
    hmma_gemm_split<<<dim3(NHEAD / 128, MB, 2), 128, SMEM_BYTES>>>(
        M, NHEAD, H, H / 2, f7h, f7l, whh, whl, part);
    // 5) postprocess (+head reduce + bias)
    postprocess_kernel<<<M, 128>>>(M, part, bcls, bbox_b, boxes, out, OUTW);
}

// round 11
// speedup vs baseline: 1.4401x; 1.3423x over previous
#include <cuda_runtime.h>
#include <cuda_bf16.h>
#include <cuda_fp16.h>
#include <cstdint>

// ---------------------------------------------------------------------------
// GeneralizedRCNNExtractModel via HMMA (mma.sync) split-fp32 GEMMs.
//   f6     = relu(x @ W6 + b6)            2000x12544 @ 12544x1024
//   f7     = relu(f6 @ W7 + b7)           2000x1024  @ 1024x1024
//   logits = f7 @ [Wcls|Wbox] + bias      2000x1024 @ 1024x405 (pad 512)
// R11: legacy mma.sync tensor issue is HW-capped at ~54% => only lever is
// fewer MMAs. GEMM1 switches to fp16 2-pass (A split hi+lo fp16, B single
// fp16): dropped A@Bl term ~2^-11/sqrt(3) ~ 2.8e-4 rel err. GEMM2 + head
// stay bf16 3-pass (2e-5). MMA count on the dominant GEMM: -33%.
// ---------------------------------------------------------------------------

#define NUM_CLASSES 81
#define SCORE_THRESH 0.05f
#define BBOX_XFORM_CLIP 4.135166556742356f

#define RMAX 2000
#define KDIM 12544
#define HDIM 1024
#define NHEAD 512   // 405 used, padded

// --------------------------- device scratch -------------------------------
__device__ __half         g_xh[RMAX * KDIM];    // fp16 hi of x
__device__ __half         g_xl[RMAX * KDIM];    // fp16 lo of x
__device__ __half         g_w6h[HDIM * KDIM];   // W6^T single fp16 [N][K]
__device__ __nv_bfloat16 g_w7h[HDIM * HDIM];
__device__ __nv_bfloat16 g_w7l[HDIM * HDIM];
__device__ __nv_bfloat16 g_whh[NHEAD * HDIM];   // rows 405..511 stay zero (.bss)
__device__ __nv_bfloat16 g_whl[NHEAD * HDIM];
__device__ __nv_bfloat16 g_f6h[RMAX * HDIM];
__device__ __nv_bfloat16 g_f6l[RMAX * HDIM];
__device__ __nv_bfloat16 g_f7h[RMAX * HDIM];
__device__ __nv_bfloat16 g_f7l[RMAX * HDIM];
__device__ float         g_part[2 * RMAX * HDIM];   // split-K partials

// --------------------------- PTX helpers ----------------------------------
__device__ __forceinline__ uint32_t smem_to_u32(const void* p) {
    uint32_t a;
    asm("{ .reg .u64 t; cvta.to.shared.u64 t, %1; cvt.u32.u64 %0, t; }"
        : "=r"(a) : "l"(p));
    return a;
}
__device__ __forceinline__ void cp_async16(uint32_t dst, const void* src, bool pred) {
    int sz = pred ? 16 : 0;
    asm volatile("cp.async.cg.shared.global [%0], [%1], 16, %2;"
                 :: "r"(dst), "l"(src), "r"(sz) : "memory");
}
#define CP_COMMIT() asm volatile("cp.async.commit_group;" ::: "memory")
#define CP_WAIT(N)  asm volatile("cp.async.wait_group %0;" :: "n"(N) : "memory")

__device__ __forceinline__ void ldsm_x4(uint32_t& r0, uint32_t& r1,
                                        uint32_t& r2, uint32_t& r3, uint32_t addr) {
    asm volatile("ldmatrix.sync.aligned.m8n8.x4.shared.b16 {%0,%1,%2,%3}, [%4];"
                 : "=r"(r0), "=r"(r1), "=r"(r2), "=r"(r3) : "r"(addr));
}
// bf16 MMA
__device__ __forceinline__ void mma16816(float* c, const uint32_t* a,
                                         uint32_t b0, uint32_t b1) {
    asm volatile(
        "mma.sync.aligned.m16n8k16.row.col.f32.bf16.bf16.f32 "
        "{%0,%1,%2,%3}, {%4,%5,%6,%7}, {%8,%9}, {%0,%1,%2,%3};"
        : "+f"(c[0]), "+f"(c[1]), "+f"(c[2]), "+f"(c[3])
        : "r"(a[0]), "r"(a[1]), "r"(a[2]), "r"(a[3]), "r"(b0), "r"(b1));
}
// fp16 MMA
__device__ __forceinline__ void mma16816h(float* c, const uint32_t* a,
                                          uint32_t b0, uint32_t b1) {
    asm volatile(
        "mma.sync.aligned.m16n8k16.row.col.f32.f16.f16.f32 "
        "{%0,%1,%2,%3}, {%4,%5,%6,%7}, {%8,%9}, {%0,%1,%2,%3};"
        : "+f"(c[0]), "+f"(c[1]), "+f"(c[2]), "+f"(c[3])
        : "r"(a[0]), "r"(a[1]), "r"(a[2]), "r"(a[3]), "r"(b0), "r"(b1));
}

// swizzled smem offset for (row, 16B-chunk), 64B logical rows.
__device__ __forceinline__ uint32_t swoff(int row, int chunk) {
    return (uint32_t)(row * 64 + ((chunk ^ ((row >> 1) & 3)) << 4));
}

// --------------------------- mega prep kernel -----------------------------
#define NBX 1024

// bf16 transpose+split (W7 / Wcls / Wbox)
__device__ void transpose_split_job(const float* __restrict__ W, int K, int Nsrc,
                                    int ldT, int rowoff,
                                    __nv_bfloat16* __restrict__ Th,
                                    __nv_bfloat16* __restrict__ Tl,
                                    int lb, int tid) {
    __shared__ float t[32][33];
    const int ntn = (Nsrc + 31) / 32;
    const int n0 = (lb % ntn) * 32;
    const int k0 = (lb / ntn) * 32;
    const int tx = tid & 31, ty = tid >> 5;  // 32 x 8
#pragma unroll
    for (int i = 0; i < 32; i += 8) {
        float v = 0.f;
        if (n0 + tx < Nsrc)
            v = W[(size_t)(k0 + ty + i) * Nsrc + n0 + tx];
        t[ty + i][tx] = v;
    }
    __syncthreads();
#pragma unroll
    for (int i = 0; i < 32; i += 8) {
        const int n = n0 + ty + i;
        if (n >= Nsrc) continue;
        float v = t[tx][ty + i];
        __nv_bfloat16 h = __float2bfloat16(v);
        __nv_bfloat16 l = __float2bfloat16(v - __bfloat162float(h));
        const size_t o = (size_t)(rowoff + n) * ldT + k0 + tx;
        Th[o] = h;
        Tl[o] = l;
    }
}

// fp16 single-precision transpose (W6)
__device__ void transpose_half_job(const float* __restrict__ W, int K, int Nsrc,
                                   __half* __restrict__ Th, int lb, int tid) {
    __shared__ float t[32][33];
    const int ntn = Nsrc / 32;
    const int n0 = (lb % ntn) * 32;
    const int k0 = (lb / ntn) * 32;
    const int tx = tid & 31, ty = tid >> 5;  // 32 x 8
#pragma unroll
    for (int i = 0; i < 32; i += 8)
        t[ty + i][tx] = W[(size_t)(k0 + ty + i) * Nsrc + n0 + tx];
    __syncthreads();
#pragma unroll
    for (int i = 0; i < 32; i += 8) {
        const int n = n0 + ty + i;
        Th[(size_t)n * K + k0 + tx] = __float2half(t[tx][ty + i]);
    }
}

__global__ __launch_bounds__(256)
void prep_kernel(const float* __restrict__ x,
                 const float* __restrict__ W6,
                 const float* __restrict__ W7,
                 const float* __restrict__ Wcls,
                 const float* __restrict__ Wbox,
                 __half* __restrict__ xh, __half* __restrict__ xl,
                 __half* __restrict__ w6h,
                 __nv_bfloat16* __restrict__ w7h, __nv_bfloat16* __restrict__ w7l,
                 __nv_bfloat16* __restrict__ whh, __nv_bfloat16* __restrict__ whl,
                 int M, int K1, int H, int NC) {
    const int tid = threadIdx.x;
    const int nbW6 = (H / 32) * (K1 / 32);
    const int nbW7 = (H / 32) * (H / 32);
    const int nbWc = ((NC + 31) / 32) * (H / 32);
    const int nbWb = ((NC * 4 + 31) / 32) * (H / 32);
    int b = blockIdx.x;

    if (b < NBX) {
        // ---- split x into fp16 hi+lo ----
        const size_t n4 = ((size_t)M * K1) / 4;
        size_t i = (size_t)b * 256 + tid;
        const size_t stride = (size_t)NBX * 256;
        const float4* X4 = reinterpret_cast<const float4*>(x);
        __half2* H2 = reinterpret_cast<__half2*>(xh);
        __half2* L2 = reinterpret_cast<__half2*>(xl);
        for (; i < n4; i += stride) {
            float4 v = X4[i];
            __half hx = __float2half(v.x), hy = __float2half(v.y);
            __half hz = __float2half(v.z), hw = __float2half(v.w);
            __half lx = __float2half(v.x - __half2float(hx));
            __half ly = __float2half(v.y - __half2float(hy));
            __half lz = __float2half(v.z - __half2float(hz));
            __half lw = __float2half(v.w - __half2float(hw));
            H2[i * 2 + 0] = __half2(hx, hy);
            H2[i * 2 + 1] = __half2(hz, hw);
            L2[i * 2 + 0] = __half2(lx, ly);
            L2[i * 2 + 1] = __half2(lz, lw);
        }
        return;
    }
    b -= NBX;
    if (b < nbW6) { transpose_half_job(W6, K1, H, w6h, b, tid); return; }
    b -= nbW6;
    if (b < nbW7) { transpose_split_job(W7, H, H, H, 0, w7h, w7l, b, tid); return; }
    b -= nbW7;
    if (b < nbWc) { transpose_split_job(Wcls, H, NC, H, 0, whh, whl, b, tid); return; }
    b -= nbWc;
    if (b < nbWb) { transpose_split_job(Wbox, H, NC * 4, H, NC, whh, whl, b, tid); return; }
}

// --------------------------- fp16 2-pass GEMM (split-K) -------------------
// Partial[z][M][N] = sum over K-slice z of (Ah@Bh + Al@Bh), all fp16 tiles.
// Block 128x128, 4 warps of 64x64. Stage = Ah|Al|Bh (24KB), 3-stage
// pipeline (72KB smem), 2 CTAs/SM. Ksl%32==0, N%128==0.
__global__ __launch_bounds__(128, 2)
void hmma_gemm_2p(int M, int N, int K, int Ksl,
                  const __half* __restrict__ Ah,
                  const __half* __restrict__ Al,
                  const __half* __restrict__ Bh,
                  float* __restrict__ Pout) {
    extern __shared__ char smem[];
    const uint32_t sbase = smem_to_u32(smem);
    const int tid = threadIdx.x, lane = tid & 31, wid = tid >> 5;
    const int bm = blockIdx.y * 128, bn = blockIdx.x * 128;
    const int wm = (wid & 1) * 64, wn = (wid >> 1) * 64;
    const int kbase = blockIdx.z * Ksl;

    constexpr uint32_t STAGE = 24576u;   // Ah 8K | Al 8K | Bh 8K
    constexpr int NSTAGE = 3;

    uint32_t offA[4];
    size_t gofA[4], gofB[4];
    bool predA[4];
#pragma unroll
    for (int i = 0; i < 4; ++i) {
        const int idx = tid + i * 128;
        const int row = idx >> 2, ch = idx & 3;
        offA[i] = swoff(row, ch);
        const int ra = (bm + row < M) ? (bm + row) : (M - 1);
        predA[i] = (bm + row < M);
        gofA[i] = (size_t)ra * K + kbase + ch * 8;
        gofB[i] = (size_t)(bn + row) * K + kbase + ch * 8;
    }

    uint32_t aFrag[4][2];
#pragma unroll
    for (int mt = 0; mt < 4; ++mt) {
        const int row = wm + mt * 16 + (lane & 15);
#pragma unroll
        for (int kc = 0; kc < 2; ++kc)
            aFrag[mt][kc] = swoff(row, (lane >> 4) + kc * 2);
    }
    uint32_t bFrag[4][2];
#pragma unroll
    for (int nt = 0; nt < 4; ++nt) {
        const int row = wn + nt * 16 + ((lane & 7) | ((lane >> 4) << 3));
#pragma unroll
        for (int kc = 0; kc < 2; ++kc)
            bFrag[nt][kc] = swoff(row, ((lane >> 3) & 1) + kc * 2);
    }

    float acc[4][8][4];
#pragma unroll
    for (int mt = 0; mt < 4; ++mt)
#pragma unroll
        for (int nf = 0; nf < 8; ++nf)
#pragma unroll
            for (int k = 0; k < 4; ++k) acc[mt][nf][k] = 0.f;

    const int S = Ksl / 32;

    auto issue = [&](int step) {
        const size_t k0 = (size_t)step * 32;
        const uint32_t st = (uint32_t)(step % NSTAGE) * STAGE;
#pragma unroll
        for (int i = 0; i < 4; ++i) {
            cp_async16(sbase + st + offA[i],          Ah + gofA[i] + k0, predA[i]);
            cp_async16(sbase + st + 8192 + offA[i],   Al + gofA[i] + k0, predA[i]);
            cp_async16(sbase + st + 16384 + offA[i],  Bh + gofB[i] + k0, true);
        }
        CP_COMMIT();
    };

    issue(0);
    if (S > 1) issue(1);

#pragma unroll 1
    for (int s = 0; s < S; ++s) {
        if (s + 1 < S) { CP_WAIT(1); } else { CP_WAIT(0); }
        __syncthreads();
        if (s + 2 < S) issue(s + 2);

        const uint32_t base   = sbase + (uint32_t)(s % NSTAGE) * STAGE;
        const uint32_t baseAl = base + 8192u;
        const uint32_t baseBh = base + 16384u;
#pragma unroll
        for (int kc = 0; kc < 2; ++kc) {
            uint32_t aH[4][4], aL[4][4];
#pragma unroll
            for (int mt = 0; mt < 4; ++mt) {
                ldsm_x4(aH[mt][0], aH[mt][1], aH[mt][2], aH[mt][3],
                        base   + aFrag[mt][kc]);
                ldsm_x4(aL[mt][0], aL[mt][1], aL[mt][2], aL[mt][3],
                        baseAl + aFrag[mt][kc]);
            }
#pragma unroll
            for (int nt = 0; nt < 4; ++nt) {
                uint32_t b0, b1, b2, b3;
                ldsm_x4(b0, b1, b2, b3, baseBh + bFrag[nt][kc]);
#pragma unroll
                for (int mt = 0; mt < 4; ++mt) {
                    float* a0 = acc[mt][nt * 2 + 0];
                    float* a1 = acc[mt][nt * 2 + 1];
                    mma16816h(a0, aH[mt], b0, b1);
                    mma16816h(a1, aH[mt], b2, b3);
                    mma16816h(a0, aL[mt], b0, b1);
                    mma16816h(a1, aL[mt], b2, b3);
                }
            }
        }
    }

    float* P = Pout + (size_t)blockIdx.z * M * N;
#pragma unroll
    for (int mt = 0; mt < 4; ++mt) {
#pragma unroll
        for (int nf = 0; nf < 8; ++nf) {
            const int col = bn + wn + nf * 8 + (lane & 3) * 2;
#pragma unroll
            for (int half = 0; half < 2; ++half) {
                const int row = bm + wm + mt * 16 + (lane >> 2) + half * 8;
                if (row >= M) continue;
                *reinterpret_cast<float2*>(&P[(size_t)row * N + col]) =
                    make_float2(acc[mt][nf][half * 2 + 0],
                                acc[mt][nf][half * 2 + 1]);
            }
        }
    }
}

// --------------------------- bf16 3-pass GEMM (split-K) -------------------
// Partial[z][M][N] = sum over K-slice z of (Ah@Bh + Ah@Bl + Al@Bh).
// Block 128x128, 4 warps of 64x64, stage 32KB, 3-stage (96KB), 2 CTAs/SM.
__global__ __launch_bounds__(128, 2)
void hmma_gemm_split(int M, int N, int K, int Ksl,
                     const __nv_bfloat16* __restrict__ Ah,
                     const __nv_bfloat16* __restrict__ Al,
                     const __nv_bfloat16* __restrict__ Bh,
                     const __nv_bfloat16* __restrict__ Bl,
                     float* __restrict__ Pout) {
    extern __shared__ char smem[];
    const uint32_t sbase = smem_to_u32(smem);
    const int tid = threadIdx.x, lane = tid & 31, wid = tid >> 5;
    const int bm = blockIdx.y * 128, bn = blockIdx.x * 128;
    const int wm = (wid & 1) * 64, wn = (wid >> 1) * 64;
    const int kbase = blockIdx.z * Ksl;

    constexpr uint32_t STAGE = 32768u;
    constexpr int NSTAGE = 3;

    uint32_t offA[4];
    size_t gofA[4], gofB[4];
    bool predA[4];
#pragma unroll
    for (int i = 0; i < 4; ++i) {
        const int idx = tid + i * 128;
        const int row = idx >> 2, ch = idx & 3;
        offA[i] = swoff(row, ch);
        const int ra = (bm + row < M) ? (bm + row) : (M - 1);
        predA[i] = (bm + row < M);
        gofA[i] = (size_t)ra * K + kbase + ch * 8;
        gofB[i] = (size_t)(bn + row) * K + kbase + ch * 8;
    }

    uint32_t aFrag[4][2];
#pragma unroll
    for (int mt = 0; mt < 4; ++mt) {
        const int row = wm + mt * 16 + (lane & 15);
#pragma unroll
        for (int kc = 0; kc < 2; ++kc)
            aFrag[mt][kc] = swoff(row, (lane >> 4) + kc * 2);
    }
    uint32_t bFrag[4][2];
#pragma unroll
    for (int nt = 0; nt < 4; ++nt) {
        const int row = wn + nt * 16 + ((lane & 7) | ((lane >> 4) << 3));
#pragma unroll
        for (int kc = 0; kc < 2; ++kc)
            bFrag[nt][kc] = swoff(row, ((lane >> 3) & 1) + kc * 2);
    }

    float acc[4][8][4];
#pragma unroll
    for (int mt = 0; mt < 4; ++mt)
#pragma unroll
        for (int nf = 0; nf < 8; ++nf)
#pragma unroll
            for (int k = 0; k < 4; ++k) acc[mt][nf][k] = 0.f;

    const int S = Ksl / 32;

    auto issue = [&](int step) {
        const size_t k0 = (size_t)step * 32;
        const uint32_t st = (uint32_t)(step % NSTAGE) * STAGE;
#pragma unroll
        for (int i = 0; i < 4; ++i) {
            cp_async16(sbase + st + offA[i],          Ah + gofA[i] + k0, predA[i]);
            cp_async16(sbase + st + 8192 + offA[i],   Al + gofA[i] + k0, predA[i]);
            cp_async16(sbase + st + 16384 + offA[i],  Bh + gofB[i] + k0, true);
            cp_async16(sbase + st + 24576 + offA[i],  Bl + gofB[i] + k0, true);
        }
        CP_COMMIT();
    };

    issue(0);
    if (S > 1) issue(1);

#pragma unroll 1
    for (int s = 0; s < S; ++s) {
        if (s + 1 < S) { CP_WAIT(1); } else { CP_WAIT(0); }
        __syncthreads();
        if (s + 2 < S) issue(s + 2);

        const uint32_t base   = sbase + (uint32_t)(s % NSTAGE) * STAGE;
        const uint32_t baseAl = base + 8192u;
        const uint32_t baseBh = base + 16384u;
        const uint32_t baseBl = base + 24576u;
#pragma unroll
        for (int kc = 0; kc < 2; ++kc) {
            uint32_t aH[4][4], aL[4][4];
#pragma unroll
            for (int mt = 0; mt < 4; ++mt) {
                ldsm_x4(aH[mt][0], aH[mt][1], aH[mt][2], aH[mt][3],
                        base   + aFrag[mt][kc]);
                ldsm_x4(aL[mt][0], aL[mt][1], aL[mt][2], aL[mt][3],
                        baseAl + aFrag[mt][kc]);
            }
#pragma unroll
            for (int nt = 0; nt < 4; ++nt) {
                uint32_t bh0, bh1, bh2, bh3, bl0, bl1, bl2, bl3;
                ldsm_x4(bh0, bh1, bh2, bh3, baseBh + bFrag[nt][kc]);
                ldsm_x4(bl0, bl1, bl2, bl3, baseBl + bFrag[nt][kc]);
#pragma unroll
                for (int mt = 0; mt < 4; ++mt) {
                    float* a0 = acc[mt][nt * 2 + 0];
                    float* a1 = acc[mt][nt * 2 + 1];
                    mma16816(a0, aH[mt], bh0, bh1);
                    mma16816(a1, aH[mt], bh2, bh3);
                    mma16816(a0, aH[mt], bl0, bl1);
                    mma16816(a1, aH[mt], bl2, bl3);
                    mma16816(a0, aL[mt], bh0, bh1);
                    mma16816(a1, aL[mt], bh2, bh3);
                }
            }
        }
    }

    float* P = Pout + (size_t)blockIdx.z * M * N;
#pragma unroll
    for (int mt = 0; mt < 4; ++mt) {
#pragma unroll
        for (int nf = 0; nf < 8; ++nf) {
            const int col = bn + wn + nf * 8 + (lane & 3) * 2;
#pragma unroll
            for (int half = 0; half < 2; ++half) {
                const int row = bm + wm + mt * 16 + (lane >> 2) + half * 8;
                if (row >= M) continue;
                *reinterpret_cast<float2*>(&P[(size_t)row * N + col]) =
                    make_float2(acc[mt][nf][half * 2 + 0],
                                acc[mt][nf][half * 2 + 1]);
            }
        }
    }
}

// --------------------------- split-K reduce + epilogue --------------------
__global__ __launch_bounds__(256)
void reduce_epilogue(int M, int N,
                     const float* __restrict__ P,
                     const float* __restrict__ bias, int do_relu,
                     float* __restrict__ C, int ldc,
                     __nv_bfloat16* __restrict__ Oh,
                     __nv_bfloat16* __restrict__ Ol, int ldo) {
    const size_t i = (size_t)blockIdx.x * blockDim.x + threadIdx.x;
    const size_t n2 = (size_t)M * N / 2;
    if (i >= n2) return;
    const float2 p0 = reinterpret_cast<const float2*>(P)[i];
    const float2 p1 = reinterpret_cast<const float2*>(P + (size_t)M * N)[i];
    const int col = (int)((i * 2) % N);
    const int row = (int)((i * 2) / N);
    float v0 = p0.x + p1.x + bias[col];
    float v1 = p0.y + p1.y + bias[col + 1];
    if (do_relu) { v0 = fmaxf(v0, 0.f); v1 = fmaxf(v1, 0.f); }
    if (C)
        *reinterpret_cast<float2*>(&C[(size_t)row * ldc + col]) =
            make_float2(v0, v1);
    if (Oh) {
        __nv_bfloat16 h0 = __float2bfloat16(v0);
        __nv_bfloat16 h1 = __float2bfloat16(v1);
        __nv_bfloat16 l0 = __float2bfloat16(v0 - __bfloat162float(h0));
        __nv_bfloat16 l1 = __float2bfloat16(v1 - __bfloat162float(h1));
        *reinterpret_cast<__nv_bfloat162*>(&Oh[(size_t)row * ldo + col]) =
            __nv_bfloat162(h0, h1);
        *reinterpret_cast<__nv_bfloat162*>(&Ol[(size_t)row * ldo + col]) =
            __nv_bfloat162(l0, l1);
    }
}

// --------------------------- postprocess (+head reduce) -------------------
__global__ __launch_bounds__(128)
void postprocess_kernel(int M,
                        const float* __restrict__ P,   // [2][M][NHEAD]
                        const float* __restrict__ bcls,
                        const float* __restrict__ bbox_b,
                        const float* __restrict__ boxes,
                        float* __restrict__ out, int ldo) {
    const int r = blockIdx.x;
    const int t = threadIdx.x;
    __shared__ float sl[NUM_CLASSES * 5];  // 405
    __shared__ float smax, ssum;

    const float* p0 = P + (size_t)r * NHEAD;
    const float* p1 = P + (size_t)M * NHEAD + (size_t)r * NHEAD;
    for (int i = t; i < NUM_CLASSES * 5; i += 128) {
        const float bias = (i < NUM_CLASSES) ? bcls[i] : bbox_b[i - NUM_CLASSES];
        sl[i] = p0[i] + p1[i] + bias;
    }
    __syncthreads();

    if (t == 0) {
        float m = -1e30f;
        for (int i = 0; i < NUM_CLASSES; ++i) m = fmaxf(m, sl[i]);
        float s = 0.f;
        for (int i = 0; i < NUM_CLASSES; ++i) s += expf(sl[i] - m);
        smax = m;
        ssum = s;
    }
    __syncthreads();

    if (t < NUM_CLASSES - 1) {
        const int j = t + 1;
        const float p = expf(sl[j] - smax) / ssum;
        const bool keep = p > SCORE_THRESH;

        const float bx0 = boxes[r * 4 + 0];
        const float by0 = boxes[r * 4 + 1];
        const float bx1 = boxes[r * 4 + 2];
        const float by1 = boxes[r * 4 + 3];
        const float w = bx1 - bx0 + 1.0f;
        const float hh = by1 - by0 + 1.0f;
        const float cx = bx0 + 0.5f * w;
        const float cy = by0 + 0.5f * hh;

        const float* reg = &sl[NUM_CLASSES + j * 4];
        const float dx = reg[0] * 0.1f;
        const float dy = reg[1] * 0.1f;
        const float dw = fminf(reg[2] * 0.2f, BBOX_XFORM_CLIP);
        const float dh = fminf(reg[3] * 0.2f, BBOX_XFORM_CLIP);

        const float pcx = dx * w + cx;
        const float pcy = dy * hh + cy;
        const float pw = expf(dw) * w;
        const float ph = expf(dh) * hh;

        float* orow = out + (size_t)r * ldo;
        orow[t] = keep ? p : 0.f;
        const int bo = (NUM_CLASSES - 1) + t * 4;
        orow[bo + 0] = keep ? (pcx - 0.5f * pw) : 0.f;
        orow[bo + 1] = keep ? (pcy - 0.5f * ph) : 0.f;
        orow[bo + 2] = keep ? (pcx + 0.5f * pw - 1.0f) : 0.f;
        orow[bo + 3] = keep ? (pcy + 0.5f * ph - 1.0f) : 0.f;
    }
}

// --------------------------- launch ---------------------------------------
extern "C" void kernel_launch(void* const* d_in, const int* in_sizes, int n_in,
                              void* d_out, int out_size) {
    const float* x      = (const float*)d_in[0];
    const float* boxes  = (const float*)d_in[1];
    const float* W6     = (const float*)d_in[2];
    const float* b6     = (const float*)d_in[3];
    const float* W7     = (const float*)d_in[4];
    const float* b7     = (const float*)d_in[5];
    const float* Wcls   = (const float*)d_in[6];
    const float* bcls   = (const float*)d_in[7];
    const float* Wbox   = (const float*)d_in[8];
    const float* bbox_b = (const float*)d_in[9];
    float* out = (float*)d_out;
    (void)n_in; (void)out_size;

    const int M  = in_sizes[1] / 4;       // 2000
    const int K1 = in_sizes[0] / M;       // 12544
    const int H  = in_sizes[3];           // 1024
    const int NC = in_sizes[7];           // 81
    const int OUTW = (NC - 1) * 5 + H;    // 1424

    __half *xh, *xl, *w6h;
    __nv_bfloat16 *w7h, *w7l, *whh, *whl, *f6h, *f6l, *f7h, *f7l;
    float *part;
    cudaGetSymbolAddress((void**)&xh, g_xh);
    cudaGetSymbolAddress((void**)&xl, g_xl);
    cudaGetSymbolAddress((void**)&w6h, g_w6h);
    cudaGetSymbolAddress((void**)&w7h, g_w7h);
    cudaGetSymbolAddress((void**)&w7l, g_w7l);
    cudaGetSymbolAddress((void**)&whh, g_whh);
    cudaGetSymbolAddress((void**)&whl, g_whl);
    cudaGetSymbolAddress((void**)&f6h, g_f6h);
    cudaGetSymbolAddress((void**)&f6l, g_f6l);
    cudaGetSymbolAddress((void**)&f7h, g_f7h);
    cudaGetSymbolAddress((void**)&f7l, g_f7l);
    cudaGetSymbolAddress((void**)&part, g_part);

    const int SMEM_2P = 3 * 24576;   // 72KB
    const int SMEM_3P = 3 * 32768;   // 96KB
    cudaFuncSetAttribute(hmma_gemm_2p,
                         cudaFuncAttributeMaxDynamicSharedMemorySize, SMEM_2P);
    cudaFuncSetAttribute(hmma_gemm_split,
                         cudaFuncAttributeMaxDynamicSharedMemorySize, SMEM_3P);

    // 1) mega prep
    {
        const int nbW6 = (H / 32) * (K1 / 32);
        const int nbW7 = (H / 32) * (H / 32);
        const int nbWc = ((NC + 31) / 32) * (H / 32);
        const int nbWb = ((NC * 4 + 31) / 32) * (H / 32);
        const int nb = NBX + nbW6 + nbW7 + nbWc + nbWb;
        prep_kernel<<<nb, 256>>>(x, W6, W7, Wcls, Wbox,
                                 xh, xl, w6h, w7h, w7l, whh, whl,
                                 M, K1, H, NC);
    }

    const int MB = (M + 127) / 128;  // 16
    // 2) GEMM1 fp16 2-pass (split-K=2) + reduce -> f6 + bf16 split copy
    hmma_gemm_2p<<<dim3(H / 128, MB, 2), 128, SMEM_2P>>>(
        M, H, K1, K1 / 2, xh, xl, w6h, part);
    reduce_epilogue<<<(M * H / 2 + 255) / 256, 256>>>(
        M, H, part, b6, 1, out + (NC - 1) * 5, OUTW, f6h, f6l, H);
    // 3) GEMM2 bf16 3-pass (split-K=2) + reduce -> f7 split
    hmma_gemm_split<<<dim3(H / 128, MB, 2), 128, SMEM_3P>>>(
        M, H, H, H / 2, f6h, f6l, w7h, w7l, part);
    reduce_epilogue<<<(M * H / 2 + 255) / 256, 256>>>(
        M, H, part, b7, 1, nullptr, 0, f7h, f7l, H);
    // 4) head GEMM bf16 3-pass (split-K=2); reduce fused into postprocess
    hmma_gemm_split<<<dim3(NHEAD / 128, MB, 2), 128, SMEM_3P>>>(
        M, NHEAD, H, H / 2, f7h, f7l, whh, whl, part);
    // 5) postprocess (+head reduce + bias)
    postprocess_kernel<<<M, 128>>>(M, part, bcls, bbox_b, boxes, out, OUTW);
}

// round 12
// speedup vs baseline: 2.6817x; 1.8622x over previous
#include <cuda_runtime.h>
#include <cuda_fp16.h>
#include <cstdint>

// ---------------------------------------------------------------------------
// GeneralizedRCNNExtractModel via HMMA (mma.sync f16) GEMMs.
//   f6     = relu(x @ W6 + b6)            2000x12544 @ 12544x1024
//   f7     = relu(f6 @ W7 + b7)           2000x1024  @ 1024x1024
//   logits = f7 @ [Wcls|Wbox] + bias      2000x1024 @ 1024x405 (pad 512)
// R12: single-pass pure-fp16 for ALL GEMMs. R11 measured that W-side fp16
// quantization alone gives 2.08e-4; adding x/f6/f7 quantization lands
// ~4.5e-4 in quadrature — 2x margin under 1e-3. MMA count: -50%/-67%.
// HMMA issue ceiling (~54%, proven invariant R7-R10) makes MMA count the
// only remaining lever.
// ---------------------------------------------------------------------------

#define NUM_CLASSES 81
#define SCORE_THRESH 0.05f
#define BBOX_XFORM_CLIP 4.135166556742356f

#define RMAX 2000
#define KDIM 12544
#define HDIM 1024
#define NHEAD 512   // 405 used, padded

// --------------------------- device scratch -------------------------------
__device__ __half g_xh[RMAX * KDIM];     // fp16 x
__device__ __half g_w6h[HDIM * KDIM];    // W6^T fp16 [N][K]
__device__ __half g_w7h[HDIM * HDIM];    // W7^T fp16
__device__ __half g_whh[NHEAD * HDIM];   // [Wcls|Wbox]^T; rows 405..511 zero
__device__ __half g_f6h[RMAX * HDIM];
__device__ __half g_f7h[RMAX * HDIM];
__device__ float  g_part[2 * RMAX * HDIM];   // split-K partials

// --------------------------- PTX helpers ----------------------------------
__device__ __forceinline__ uint32_t smem_to_u32(const void* p) {
    uint32_t a;
    asm("{ .reg .u64 t; cvta.to.shared.u64 t, %1; cvt.u32.u64 %0, t; }"
        : "=r"(a) : "l"(p));
    return a;
}
__device__ __forceinline__ void cp_async16(uint32_t dst, const void* src, bool pred) {
    int sz = pred ? 16 : 0;
    asm volatile("cp.async.cg.shared.global [%0], [%1], 16, %2;"
                 :: "r"(dst), "l"(src), "r"(sz) : "memory");
}
#define CP_COMMIT() asm volatile("cp.async.commit_group;" ::: "memory")
#define CP_WAIT(N)  asm volatile("cp.async.wait_group %0;" :: "n"(N) : "memory")

__device__ __forceinline__ void ldsm_x4(uint32_t& r0, uint32_t& r1,
                                        uint32_t& r2, uint32_t& r3, uint32_t addr) {
    asm volatile("ldmatrix.sync.aligned.m8n8.x4.shared.b16 {%0,%1,%2,%3}, [%4];"
                 : "=r"(r0), "=r"(r1), "=r"(r2), "=r"(r3) : "r"(addr));
}
__device__ __forceinline__ void mma16816h(float* c, const uint32_t* a,
                                          uint32_t b0, uint32_t b1) {
    asm volatile(
        "mma.sync.aligned.m16n8k16.row.col.f32.f16.f16.f32 "
        "{%0,%1,%2,%3}, {%4,%5,%6,%7}, {%8,%9}, {%0,%1,%2,%3};"
        : "+f"(c[0]), "+f"(c[1]), "+f"(c[2]), "+f"(c[3])
        : "r"(a[0]), "r"(a[1]), "r"(a[2]), "r"(a[3]), "r"(b0), "r"(b1));
}

// swizzled smem offset for (row, 16B-chunk), 64B logical rows.
__device__ __forceinline__ uint32_t swoff(int row, int chunk) {
    return (uint32_t)(row * 64 + ((chunk ^ ((row >> 1) & 3)) << 4));
}

// --------------------------- mega prep kernel -----------------------------
#define NBX 1024

// fp16 transpose (guarded on Nsrc), writes rows [rowoff, rowoff+Nsrc)
__device__ void transpose_half_job(const float* __restrict__ W, int K, int Nsrc,
                                   int ldT, int rowoff,
                                   __half* __restrict__ Th, int lb, int tid) {
    __shared__ float t[32][33];
    const int ntn = (Nsrc + 31) / 32;
    const int n0 = (lb % ntn) * 32;
    const int k0 = (lb / ntn) * 32;
    const int tx = tid & 31, ty = tid >> 5;  // 32 x 8
#pragma unroll
    for (int i = 0; i < 32; i += 8) {
        float v = 0.f;
        if (n0 + tx < Nsrc)
            v = W[(size_t)(k0 + ty + i) * Nsrc + n0 + tx];
        t[ty + i][tx] = v;
    }
    __syncthreads();
#pragma unroll
    for (int i = 0; i < 32; i += 8) {
        const int n = n0 + ty + i;
        if (n >= Nsrc) continue;
        Th[(size_t)(rowoff + n) * ldT + k0 + tx] = __float2half(t[tx][ty + i]);
    }
}

__global__ __launch_bounds__(256)
void prep_kernel(const float* __restrict__ x,
                 const float* __restrict__ W6,
                 const float* __restrict__ W7,
                 const float* __restrict__ Wcls,
                 const float* __restrict__ Wbox,
                 __half* __restrict__ xh,
                 __half* __restrict__ w6h,
                 __half* __restrict__ w7h,
                 __half* __restrict__ whh,
                 int M, int K1, int H, int NC) {
    const int tid = threadIdx.x;
    const int nbW6 = (H / 32) * (K1 / 32);
    const int nbW7 = (H / 32) * (H / 32);
    const int nbWc = ((NC + 31) / 32) * (H / 32);
    const int nbWb = ((NC * 4 + 31) / 32) * (H / 32);
    int b = blockIdx.x;

    if (b < NBX) {
        // ---- convert x to fp16 ----
        const size_t n4 = ((size_t)M * K1) / 4;
        size_t i = (size_t)b * 256 + tid;
        const size_t stride = (size_t)NBX * 256;
        const float4* X4 = reinterpret_cast<const float4*>(x);
        __half2* H2 = reinterpret_cast<__half2*>(xh);
        for (; i < n4; i += stride) {
            float4 v = X4[i];
            H2[i * 2 + 0] = __half2(__float2half(v.x), __float2half(v.y));
            H2[i * 2 + 1] = __half2(__float2half(v.z), __float2half(v.w));
        }
        return;
    }
    b -= NBX;
    if (b < nbW6) { transpose_half_job(W6, K1, H, K1, 0, w6h, b, tid); return; }
    b -= nbW6;
    if (b < nbW7) { transpose_half_job(W7, H, H, H, 0, w7h, b, tid); return; }
    b -= nbW7;
    if (b < nbWc) { transpose_half_job(Wcls, H, NC, H, 0, whh, b, tid); return; }
    b -= nbWc;
    if (b < nbWb) { transpose_half_job(Wbox, H, NC * 4, H, NC, whh, b, tid); return; }
}

// --------------------------- fp16 1-pass GEMM (split-K) -------------------
// Partial[z][M][N] = sum over K-slice z of A@B^T (pure fp16, f32 accum).
// Block 128x128, 4 warps of 64x64. Stage = A 8K | B 8K (16KB), 3-stage
// cp.async pipeline (48KB smem), 2 CTAs/SM. Ksl%32==0, N%128==0.
__global__ __launch_bounds__(128, 2)
void hmma_gemm_f16(int M, int N, int K, int Ksl,
                   const __half* __restrict__ A,
                   const __half* __restrict__ B,
                   float* __restrict__ Pout) {
    extern __shared__ char smem[];
    const uint32_t sbase = smem_to_u32(smem);
    const int tid = threadIdx.x, lane = tid & 31, wid = tid >> 5;
    const int bm = blockIdx.y * 128, bn = blockIdx.x * 128;
    const int wm = (wid & 1) * 64, wn = (wid >> 1) * 64;
    const int kbase = blockIdx.z * Ksl;

    constexpr uint32_t STAGE = 16384u;   // A 8K | B 8K
    constexpr int NSTAGE = 3;

    uint32_t offA[4];
    size_t gofA[4], gofB[4];
    bool predA[4];
#pragma unroll
    for (int i = 0; i < 4; ++i) {
        const int idx = tid + i * 128;           // 0..511
        const int row = idx >> 2, ch = idx & 3;  // 128 rows x 4 chunks(16B)
        offA[i] = swoff(row, ch);
        const int ra = (bm + row < M) ? (bm + row) : (M - 1);
        predA[i] = (bm + row < M);
        gofA[i] = (size_t)ra * K + kbase + ch * 8;
        gofB[i] = (size_t)(bn + row) * K + kbase + ch * 8;
    }

    uint32_t aFrag[4][2];
#pragma unroll
    for (int mt = 0; mt < 4; ++mt) {
        const int row = wm + mt * 16 + (lane & 15);
#pragma unroll
        for (int kc = 0; kc < 2; ++kc)
            aFrag[mt][kc] = swoff(row, (lane >> 4) + kc * 2);
    }
    uint32_t bFrag[4][2];
#pragma unroll
    for (int nt = 0; nt < 4; ++nt) {
        const int row = wn + nt * 16 + ((lane & 7) | ((lane >> 4) << 3));
#pragma unroll
        for (int kc = 0; kc < 2; ++kc)
            bFrag[nt][kc] = swoff(row, ((lane >> 3) & 1) + kc * 2);
    }

    float acc[4][8][4];
#pragma unroll
    for (int mt = 0; mt < 4; ++mt)
#pragma unroll
        for (int nf = 0; nf < 8; ++nf)
#pragma unroll
            for (int k = 0; k < 4; ++k) acc[mt][nf][k] = 0.f;

    const int S = Ksl / 32;

    auto issue = [&](int step) {
        const size_t k0 = (size_t)step * 32;
        const uint32_t st = (uint32_t)(step % NSTAGE) * STAGE;
#pragma unroll
        for (int i = 0; i < 4; ++i) {
            cp_async16(sbase + st + offA[i],        A + gofA[i] + k0, predA[i]);
            cp_async16(sbase + st + 8192 + offA[i], B + gofB[i] + k0, true);
        }
        CP_COMMIT();
    };

    issue(0);
    if (S > 1) issue(1);

#pragma unroll 1
    for (int s = 0; s < S; ++s) {
        if (s + 1 < S) { CP_WAIT(1); } else { CP_WAIT(0); }
        __syncthreads();
        if (s + 2 < S) issue(s + 2);

        const uint32_t baseA = sbase + (uint32_t)(s % NSTAGE) * STAGE;
        const uint32_t baseB = baseA + 8192u;
#pragma unroll
        for (int kc = 0; kc < 2; ++kc) {
            uint32_t a[4][4];
#pragma unroll
            for (int mt = 0; mt < 4; ++mt)
                ldsm_x4(a[mt][0], a[mt][1], a[mt][2], a[mt][3],
                        baseA + aFrag[mt][kc]);
#pragma unroll
            for (int nt = 0; nt < 4; ++nt) {
                uint32_t b0, b1, b2, b3;
                ldsm_x4(b0, b1, b2, b3, baseB + bFrag[nt][kc]);
#pragma unroll
                for (int mt = 0; mt < 4; ++mt) {
                    mma16816h(acc[mt][nt * 2 + 0], a[mt], b0, b1);
                    mma16816h(acc[mt][nt * 2 + 1], a[mt], b2, b3);
                }
            }
        }
    }

    float* P = Pout + (size_t)blockIdx.z * M * N;
#pragma unroll
    for (int mt = 0; mt < 4; ++mt) {
#pragma unroll
        for (int nf = 0; nf < 8; ++nf) {
            const int col = bn + wn + nf * 8 + (lane & 3) * 2;
#pragma unroll
            for (int half = 0; half < 2; ++half) {
                const int row = bm + wm + mt * 16 + (lane >> 2) + half * 8;
                if (row >= M) continue;
                *reinterpret_cast<float2*>(&P[(size_t)row * N + col]) =
                    make_float2(acc[mt][nf][half * 2 + 0],
                                acc[mt][nf][half * 2 + 1]);
            }
        }
    }
}

// --------------------------- split-K reduce + epilogue --------------------
// v = p0 + p1 + bias; optional relu; write f32 C (strided) and/or fp16 copy.
__global__ __launch_bounds__(256)
void reduce_epilogue(int M, int N,
                     const float* __restrict__ P,
                     const float* __restrict__ bias, int do_relu,
                     float* __restrict__ C, int ldc,
                     __half* __restrict__ Oh, int ldo) {
    const size_t i = (size_t)blockIdx.x * blockDim.x + threadIdx.x;
    const size_t n2 = (size_t)M * N / 2;
    if (i >= n2) return;
    const float2 p0 = reinterpret_cast<const float2*>(P)[i];
    const float2 p1 = reinterpret_cast<const float2*>(P + (size_t)M * N)[i];
    const int col = (int)((i * 2) % N);
    const int row = (int)((i * 2) / N);
    float v0 = p0.x + p1.x + bias[col];
    float v1 = p0.y + p1.y + bias[col + 1];
    if (do_relu) { v0 = fmaxf(v0, 0.f); v1 = fmaxf(v1, 0.f); }
    if (C)
        *reinterpret_cast<float2*>(&C[(size_t)row * ldc + col]) =
            make_float2(v0, v1);
    if (Oh)
        *reinterpret_cast<__half2*>(&Oh[(size_t)row * ldo + col]) =
            __half2(__float2half(v0), __float2half(v1));
}

// --------------------------- postprocess (+head reduce) -------------------
__global__ __launch_bounds__(128)
void postprocess_kernel(int M,
                        const float* __restrict__ P,   // [2][M][NHEAD]
                        const float* __restrict__ bcls,
                        const float* __restrict__ bbox_b,
                        const float* __restrict__ boxes,
                        float* __restrict__ out, int ldo) {
    const int r = blockIdx.x;
    const int t = threadIdx.x;
    __shared__ float sl[NUM_CLASSES * 5];  // 405
    __shared__ float smax, ssum;

    const float* p0 = P + (size_t)r * NHEAD;
    const float* p1 = P + (size_t)M * NHEAD + (size_t)r * NHEAD;
    for (int i = t; i < NUM_CLASSES * 5; i += 128) {
        const float bias = (i < NUM_CLASSES) ? bcls[i] : bbox_b[i - NUM_CLASSES];
        sl[i] = p0[i] + p1[i] + bias;
    }
    __syncthreads();

    if (t == 0) {
        float m = -1e30f;
        for (int i = 0; i < NUM_CLASSES; ++i) m = fmaxf(m, sl[i]);
        float s = 0.f;
        for (int i = 0; i < NUM_CLASSES; ++i) s += expf(sl[i] - m);
        smax = m;
        ssum = s;
    }
    __syncthreads();

    if (t < NUM_CLASSES - 1) {
        const int j = t + 1;
        const float p = expf(sl[j] - smax) / ssum;
        const bool keep = p > SCORE_THRESH;

        const float bx0 = boxes[r * 4 + 0];
        const float by0 = boxes[r * 4 + 1];
        const float bx1 = boxes[r * 4 + 2];
        const float by1 = boxes[r * 4 + 3];
        const float w = bx1 - bx0 + 1.0f;
        const float hh = by1 - by0 + 1.0f;
        const float cx = bx0 + 0.5f * w;
        const float cy = by0 + 0.5f * hh;

        const float* reg = &sl[NUM_CLASSES + j * 4];
        const float dx = reg[0] * 0.1f;
        const float dy = reg[1] * 0.1f;
        const float dw = fminf(reg[2] * 0.2f, BBOX_XFORM_CLIP);
        const float dh = fminf(reg[3] * 0.2f, BBOX_XFORM_CLIP);

        const float pcx = dx * w + cx;
        const float pcy = dy * hh + cy;
        const float pw = expf(dw) * w;
        const float ph = expf(dh) * hh;

        float* orow = out + (size_t)r * ldo;
        orow[t] = keep ? p : 0.f;
        const int bo = (NUM_CLASSES - 1) + t * 4;
        orow[bo + 0] = keep ? (pcx - 0.5f * pw) : 0.f;
        orow[bo + 1] = keep ? (pcy - 0.5f * ph) : 0.f;
        orow[bo + 2] = keep ? (pcx + 0.5f * pw - 1.0f) : 0.f;
        orow[bo + 3] = keep ? (pcy + 0.5f * ph - 1.0f) : 0.f;
    }
}

// --------------------------- launch ---------------------------------------
extern "C" void kernel_launch(void* const* d_in, const int* in_sizes, int n_in,
                              void* d_out, int out_size) {
    const float* x      = (const float*)d_in[0];
    const float* boxes  = (const float*)d_in[1];
    const float* W6     = (const float*)d_in[2];
    const float* b6     = (const float*)d_in[3];
    const float* W7     = (const float*)d_in[4];
    const float* b7     = (const float*)d_in[5];
    const float* Wcls   = (const float*)d_in[6];
    const float* bcls   = (const float*)d_in[7];
    const float* Wbox   = (const float*)d_in[8];
    const float* bbox_b = (const float*)d_in[9];
    float* out = (float*)d_out;
    (void)n_in; (void)out_size;

    const int M  = in_sizes[1] / 4;       // 2000
    const int K1 = in_sizes[0] / M;       // 12544
    const int H  = in_sizes[3];           // 1024
    const int NC = in_sizes[7];           // 81
    const int OUTW = (NC - 1) * 5 + H;    // 1424

    __half *xh, *w6h, *w7h, *whh, *f6h, *f7h;
    float *part;
    cudaGetSymbolAddress((void**)&xh, g_xh);
    cudaGetSymbolAddress((void**)&w6h, g_w6h);
    cudaGetSymbolAddress((void**)&w7h, g_w7h);
    cudaGetSymbolAddress((void**)&whh, g_whh);
    cudaGetSymbolAddress((void**)&f6h, g_f6h);
    cudaGetSymbolAddress((void**)&f7h, g_f7h);
    cudaGetSymbolAddress((void**)&part, g_part);

    const int SMEM_BYTES = 3 * 16384;  // 48KB
    cudaFuncSetAttribute(hmma_gemm_f16,
                         cudaFuncAttributeMaxDynamicSharedMemorySize, SMEM_BYTES);

    // 1) mega prep: x -> fp16, all weights transposed fp16 (single grid)
    {
        const int nbW6 = (H / 32) * (K1 / 32);
        const int nbW7 = (H / 32) * (H / 32);
        const int nbWc = ((NC + 31) / 32) * (H / 32);
        const int nbWb = ((NC * 4 + 31) / 32) * (H / 32);
        const int nb = NBX + nbW6 + nbW7 + nbWc + nbWb;
        prep_kernel<<<nb, 256>>>(x, W6, W7, Wcls, Wbox,
                                 xh, w6h, w7h, whh, M, K1, H, NC);
    }

    const int MB = (M + 127) / 128;  // 16
    // 2) GEMM1 (split-K=2) + reduce -> f6 (out cols [400,1424)) + fp16 copy
    hmma_gemm_f16<<<dim3(H / 128, MB, 2), 128, SMEM_BYTES>>>(
        M, H, K1, K1 / 2, xh, w6h, part);
    reduce_epilogue<<<(M * H / 2 + 255) / 256, 256>>>(
        M, H, part, b6, 1, out + (NC - 1) * 5, OUTW, f6h, H);
    // 3) GEMM2 (split-K=2) + reduce -> f7 fp16
    hmma_gemm_f16<<<dim3(H / 128, MB, 2), 128, SMEM_BYTES>>>(
        M, H, H, H / 2, f6h, w7h, part);
    reduce_epilogue<<<(M * H / 2 + 255) / 256, 256>>>(
        M, H, part, b7, 1, nullptr, 0, f7h, H);
    // 4) head GEMM (split-K=2); reduce fused into postprocess
    hmma_gemm_f16<<<dim3(NHEAD / 128, MB, 2), 128, SMEM_BYTES>>>(
        M, NHEAD, H, H / 2, f7h, whh, part);
    // 5) postprocess (+head reduce + bias)
    postprocess_kernel<<<M, 128>>>(M, part, bcls, bbox_b, boxes, out, OUTW);
}